// round 14
// baseline (speedup 1.0000x reference)
#include <cuda_runtime.h>
#include <cuda_fp16.h>
#include <cstdint>

#define BATCH 16
#define HW    262144

// ---------------- scratch (device globals; no runtime allocation) ----------
// q,k packed rows: per (b,h), 1024 fp16 = 16 groups x (32 hi | 32 lo), k-permuted
__device__ __half g_qp[(size_t)BATCH * 512 * 1024];
__device__ __half g_kp[(size_t)BATCH * 512 * 1024];
__device__ __half g_vT[(size_t)BATCH * 8 * HW];     // [B,C,W,H] h 64-group-permuted
__device__ float  g_attn[(size_t)BATCH * HW];       // fp32 logits [B,H,H]
__device__ __half g_at16[(size_t)BATCH * HW];       // fp16 attn, j 64-group-permuted

// ---------------- helpers ---------------------------------------------------
__device__ __forceinline__ int fp_t(int kk) { return (kk & 7) >> 1; }
__device__ __forceinline__ int fp_j(int kk) { return ((kk >> 3) << 1) | (kk & 1); }
__device__ __forceinline__ int pos32(int k32) {
    const int s = k32 >> 4, kk = k32 & 15;
    return fp_t(kk) * 8 + s * 4 + fp_j(kk);
}
__device__ __forceinline__ int pos64(int k64) {
    const int s = k64 >> 4, kk = k64 & 15;
    return ((s & 2) << 4) + fp_t(kk) * 8 + ((s & 1) << 2) + fp_j(kk);
}
template <int SO, int GO>
__device__ __forceinline__ void cpa(uint32_t s, const __half* g) {
    asm volatile("cp.async.cg.shared.global [%0+%1], [%2+%3], 16;"
                 :: "r"(s), "n"(SO), "l"(g), "n"(GO) : "memory");
}
#define CPA_COMMIT()  asm volatile("cp.async.commit_group;" ::: "memory")
#define CPA_WAIT0()   asm volatile("cp.async.wait_group 0;" ::: "memory")

__device__ __forceinline__ uint32_t smem_u32(const void* p) {
    uint32_t a;
    asm("{ .reg .u64 t; cvta.to.shared.u64 t, %1; cvt.u32.u64 %0, t; }" : "=r"(a) : "l"(p));
    return a;
}
__device__ __forceinline__ uint32_t swz128(int r, int ch) {
    const int f = ((r & 1) << 2) | ((r >> 1) & 3);
    return (uint32_t)(r * 128 + ((ch ^ f) << 4));
}
__device__ __forceinline__ uint4 lds128(uint32_t a) {
    uint4 v;
    asm volatile("ld.shared.v4.b32 {%0,%1,%2,%3}, [%4];"
                 : "=r"(v.x), "=r"(v.y), "=r"(v.z), "=r"(v.w) : "r"(a));
    return v;
}
__device__ __forceinline__ uint4 ldg128(const __half* p) {
    return __ldg((const uint4*)p);
}
#define MMAH(c, a0, a1, a2, a3, b0, b1) \
    asm volatile("mma.sync.aligned.m16n8k16.row.col.f32.f16.f16.f32 " \
                 "{%0,%1,%2,%3},{%4,%5,%6,%7},{%8,%9},{%0,%1,%2,%3};" \
                 : "+f"((c)[0]), "+f"((c)[1]), "+f"((c)[2]), "+f"((c)[3]) \
                 : "r"(a0), "r"(a1), "r"(a2), "r"(a3), "r"(b0), "r"(b1))

// ---------------------------------------------------------------------------
// Fused q/k/v 1x1 convs -> fp16 operands in GEMM-ready permuted layouts.
// ---------------------------------------------------------------------------
__global__ void __launch_bounds__(256)
qkv_kernel(const float* __restrict__ x,
           const float* __restrict__ Wq, const float* __restrict__ bq,
           const float* __restrict__ Wk, const float* __restrict__ bk,
           const float* __restrict__ Wv, const float* __restrict__ bv)
{
    __shared__ float sWq[8], sWk[8], sWv[64], sBv[8], sB2[2];
    __shared__ __half sv[8][32][33];
    const int tid = threadIdx.x;
    if (tid < 8) { sWq[tid] = Wq[tid]; sWk[tid] = Wk[tid]; sBv[tid] = bv[tid]; }
    if (tid >= 8 && tid < 72) sWv[tid - 8] = Wv[tid - 8];
    if (tid == 72) sB2[0] = bq[0];
    if (tid == 73) sB2[1] = bk[0];
    __syncthreads();

    const int b = blockIdx.z, h0 = blockIdx.y * 32, w0 = blockIdx.x * 32;
    const int j = tid & 31, i0 = tid >> 5;

    for (int ii = 0; ii < 4; ii++) {
        const int i = i0 + ii * 8;
        const int h = h0 + i, w = w0 + j;
        const size_t pb = ((size_t)b * 8) * HW + (size_t)h * 512 + w;
        float xv[8];
#pragma unroll
        for (int c = 0; c < 8; c++) xv[c] = x[pb + (size_t)c * HW];

        float q = sB2[0], k = sB2[1];
#pragma unroll
        for (int c = 0; c < 8; c++) { q += xv[c] * sWq[c]; k += xv[c] * sWk[c]; }
        const int g = w >> 5;
        const size_t base = ((size_t)b * 512 + h) * 1024 + g * 64 + pos32(w & 31);
        const __half qh = __float2half_rn(q);
        const __half kh = __float2half_rn(k);
        g_qp[base] = qh; g_qp[base + 32] = __float2half_rn(q - __half2float(qh));
        g_kp[base] = kh; g_kp[base + 32] = __float2half_rn(k - __half2float(kh));

#pragma unroll
        for (int o = 0; o < 8; o++) {
            float v = sBv[o];
#pragma unroll
            for (int c = 0; c < 8; c++) v += xv[c] * sWv[o * 8 + c];
            sv[o][i][j] = __float2half_rn(v);
        }
    }
    __syncthreads();

    for (int ii = 0; ii < 4; ii++) {
        const int wl = i0 + ii * 8;
        const int hl = j;
        const int h = h0 + hl;
        const int pp = (h & ~63) + pos64(h & 63);
#pragma unroll
        for (int c = 0; c < 8; c++) {
            g_vT[(((size_t)b * 8 + c) * 512 + (w0 + wl)) * 512 + pp] = sv[c][hl][wl];
        }
    }
}

// ---------------------------------------------------------------------------
// GEMM1 (logits, fp16 hi/lo 3-pass).  256 thr, 8 warps 4(m)x2(n), tile 32x64.
// A (q) fragments loaded straight from GMEM via LDG.128; only B in smem.
// 2-stage double buffer: 16KB/stage -> 32KB smem.
// ---------------------------------------------------------------------------
__global__ void __launch_bounds__(256, 2)
gemm_logits(const __half* __restrict__ Ab, const __half* __restrict__ Bb,
            float* __restrict__ Cb)
{
    constexpr uint32_t SB = 16384;

    extern __shared__ char smem[];
    const uint32_t s0 = smem_u32(smem);

    const int tid  = threadIdx.x;
    const int lane = tid & 31;
    const int wid  = tid >> 5;
    const int wm   = (wid & 3) * 32;
    const int wn   = (wid >> 2) * 64;
    const int gid  = lane >> 2;
    const int tig  = lane & 3;

    const int z = blockIdx.z;
    const size_t m0 = (size_t)blockIdx.y * 128;
    const size_t n0 = (size_t)blockIdx.x * 128;
    const __half* A = Ab + (size_t)z * 512 * 1024;
    const __half* B = Bb + (size_t)z * 512 * 1024;
    float* C = Cb + (size_t)z * HW;

    const uint32_t Bh = s0 + swz128(wn + gid, tig);
    const uint32_t Bl = s0 + swz128(wn + gid, 4 + tig);

    // A fragment GMEM base: row (m0+wm+gid), chunk offset c*64 fp16
    const __half* Aptr = A + (m0 + wm + gid) * 1024 + tig * 8;

    const int seg  = tid & 7;
    const int row0 = tid >> 3;
    const uint32_t lw = s0 + swz128(row0, seg);
    const __half* Bp = B + (n0 + row0) * 1024 + seg * 8;

#define GLOADL(SOFF) do { \
    cpa<(SOFF)+0,          0>(lw, Bp); cpa<(SOFF)+4096,   65536>(lw, Bp); \
    cpa<(SOFF)+8192,  131072>(lw, Bp); cpa<(SOFF)+12288, 196608>(lw, Bp); \
    Bp += 64; } while (0)

    float acc[2][8][4] = {};

    // a[0..3] = hi rows gid,+8,+16,+24 ; a[4..7] = lo
    auto ldA = [&](int c, uint4* a) {
        const __half* p = Aptr + c * 64;
#pragma unroll
        for (int r = 0; r < 4; r++) {
            a[r]     = ldg128(p + r * 8 * 1024);
            a[4 + r] = ldg128(p + r * 8 * 1024 + 32);
        }
    };

    auto compute = [&](const uint32_t SC, const uint4* a) {
        const uint4 &h0 = a[0], &h1 = a[1], &h2 = a[2], &h3 = a[3];
        const uint4 &l0 = a[4], &l1 = a[5], &l2 = a[6], &l3 = a[7];
#pragma unroll
        for (int q = 0; q < 4; q++) {
            uint4 bh[2], bl[2];
#pragma unroll
            for (int i = 0; i < 2; i++) {
                bh[i] = lds128(Bh + SC + (q * 2 + i) * 1024);
                bl[i] = lds128(Bl + SC + (q * 2 + i) * 1024);
            }
#pragma unroll
            for (int i = 0; i < 2; i++) MMAH(acc[0][q*2+i], h0.x, h1.x, h0.y, h1.y, bh[i].x, bh[i].y);
#pragma unroll
            for (int i = 0; i < 2; i++) MMAH(acc[1][q*2+i], h2.x, h3.x, h2.y, h3.y, bh[i].x, bh[i].y);
#pragma unroll
            for (int i = 0; i < 2; i++) MMAH(acc[0][q*2+i], l0.x, l1.x, l0.y, l1.y, bh[i].x, bh[i].y);
#pragma unroll
            for (int i = 0; i < 2; i++) MMAH(acc[1][q*2+i], l2.x, l3.x, l2.y, l3.y, bh[i].x, bh[i].y);
#pragma unroll
            for (int i = 0; i < 2; i++) MMAH(acc[0][q*2+i], h0.x, h1.x, h0.y, h1.y, bl[i].x, bl[i].y);
#pragma unroll
            for (int i = 0; i < 2; i++) MMAH(acc[1][q*2+i], h2.x, h3.x, h2.y, h3.y, bl[i].x, bl[i].y);
#pragma unroll
            for (int i = 0; i < 2; i++) MMAH(acc[0][q*2+i], h0.z, h1.z, h0.w, h1.w, bh[i].z, bh[i].w);
#pragma unroll
            for (int i = 0; i < 2; i++) MMAH(acc[1][q*2+i], h2.z, h3.z, h2.w, h3.w, bh[i].z, bh[i].w);
#pragma unroll
            for (int i = 0; i < 2; i++) MMAH(acc[0][q*2+i], l0.z, l1.z, l0.w, l1.w, bh[i].z, bh[i].w);
#pragma unroll
            for (int i = 0; i < 2; i++) MMAH(acc[1][q*2+i], l2.z, l3.z, l2.w, l3.w, bh[i].z, bh[i].w);
#pragma unroll
            for (int i = 0; i < 2; i++) MMAH(acc[0][q*2+i], h0.z, h1.z, h0.w, h1.w, bl[i].z, bl[i].w);
#pragma unroll
            for (int i = 0; i < 2; i++) MMAH(acc[1][q*2+i], h2.z, h3.z, h2.w, h3.w, bl[i].z, bl[i].w);
        }
    };

    uint4 a[8];
    GLOADL(0); CPA_COMMIT();
    for (int c = 0; c < 16; c += 2) {
        ldA(c, a);
        CPA_WAIT0(); __syncthreads();
        if (c + 1 < 16) GLOADL(SB);
        CPA_COMMIT();
        compute(0, a);
        ldA(c + 1, a);
        CPA_WAIT0(); __syncthreads();
        if (c + 2 < 16) GLOADL(0);
        CPA_COMMIT();
        compute(SB, a);
    }
#undef GLOADL

#pragma unroll
    for (int mt = 0; mt < 2; mt++) {
        const size_t r0 = m0 + wm + mt * 16 + gid;
#pragma unroll
        for (int nt = 0; nt < 8; nt++) {
            const size_t cc = n0 + wn + nt * 8 + tig * 2;
            *(float2*)(C + r0 * 512 + cc)       = make_float2(acc[mt][nt][0], acc[mt][nt][1]);
            *(float2*)(C + (r0 + 8) * 512 + cc) = make_float2(acc[mt][nt][2], acc[mt][nt][3]);
        }
    }
}

// ---------------------------------------------------------------------------
// GEMM2 (out = attn @ vT), fp16.  A (attn) fragments via GMEM LDG.128
// (L2-shared across the 8 channel-CTAs); only B (vT) staged in smem.
// ---------------------------------------------------------------------------
__global__ void __launch_bounds__(256, 2)
gemm_out(const __half* __restrict__ Ab, const __half* __restrict__ Bb,
         float* __restrict__ Cb)
{
    constexpr uint32_t SB = 16384;

    extern __shared__ char smem[];
    const uint32_t s0 = smem_u32(smem);

    const int tid  = threadIdx.x;
    const int lane = tid & 31;
    const int wid  = tid >> 5;
    const int wm   = (wid & 3) * 32;
    const int wn   = (wid >> 2) * 64;
    const int gid  = lane >> 2;
    const int tig  = lane & 3;

    const int z = blockIdx.z;
    const size_t m0 = (size_t)blockIdx.y * 128;
    const size_t n0 = (size_t)blockIdx.x * 128;
    const __half* A = Ab + (size_t)(z >> 3) * HW;
    const __half* B = Bb + (size_t)z * HW;
    float* C = Cb + (size_t)z * HW;

    const uint32_t B0 = s0 + swz128(wn + gid, tig);
    const uint32_t B1 = s0 + swz128(wn + gid, 4 + tig);

    const __half* Aptr = A + (m0 + wm + gid) * 512 + tig * 8;

    const int seg  = tid & 7;
    const int row0 = tid >> 3;
    const uint32_t lw = s0 + swz128(row0, seg);
    const __half* Bp = B + (n0 + row0) * 512 + seg * 8;

#define GLOAD(SOFF) do { \
    cpa<(SOFF)+0,          0>(lw, Bp); cpa<(SOFF)+4096,   32768>(lw, Bp); \
    cpa<(SOFF)+8192,   65536>(lw, Bp); cpa<(SOFF)+12288,  98304>(lw, Bp); \
    Bp += 64; } while (0)

    float acc[2][8][4] = {};

    // a[0..3] = g0 rows gid,+8,+16,+24 ; a[4..7] = g1 (+64B)
    auto ldA = [&](int c, uint4* a) {
        const __half* p = Aptr + c * 64;
#pragma unroll
        for (int r = 0; r < 4; r++) {
            a[r]     = ldg128(p + r * 8 * 512);
            a[4 + r] = ldg128(p + r * 8 * 512 + 32);
        }
    };

    auto compute = [&](const uint32_t SC, const uint4* a) {
#pragma unroll
        for (int g = 0; g < 2; g++) {
            const uint32_t bB = (g ? B1 : B0) + SC;
            const uint4 &a0 = a[g*4], &a1 = a[g*4+1], &a2 = a[g*4+2], &a3 = a[g*4+3];
#pragma unroll
            for (int h = 0; h < 2; h++) {
                uint4 bv[4];
#pragma unroll
                for (int i = 0; i < 4; i++) bv[i] = lds128(bB + (h * 4 + i) * 1024);
#pragma unroll
                for (int i = 0; i < 4; i++)
                    MMAH(acc[0][h*4+i], a0.x, a1.x, a0.y, a1.y, bv[i].x, bv[i].y);
#pragma unroll
                for (int i = 0; i < 4; i++)
                    MMAH(acc[1][h*4+i], a2.x, a3.x, a2.y, a3.y, bv[i].x, bv[i].y);
#pragma unroll
                for (int i = 0; i < 4; i++)
                    MMAH(acc[0][h*4+i], a0.z, a1.z, a0.w, a1.w, bv[i].z, bv[i].w);
#pragma unroll
                for (int i = 0; i < 4; i++)
                    MMAH(acc[1][h*4+i], a2.z, a3.z, a2.w, a3.w, bv[i].z, bv[i].w);
            }
        }
    };

    uint4 a[8];
    GLOAD(0); CPA_COMMIT();
    for (int c = 0; c < 8; c += 2) {
        ldA(c, a);
        CPA_WAIT0(); __syncthreads();
        if (c + 1 < 8) GLOAD(SB);
        CPA_COMMIT();
        compute(0, a);
        ldA(c + 1, a);
        CPA_WAIT0(); __syncthreads();
        if (c + 2 < 8) GLOAD(0);
        CPA_COMMIT();
        compute(SB, a);
    }
#undef GLOAD

#pragma unroll
    for (int mt = 0; mt < 2; mt++) {
        const size_t r0 = m0 + wm + mt * 16 + gid;
#pragma unroll
        for (int nt = 0; nt < 8; nt++) {
            const size_t cc = n0 + wn + nt * 8 + tig * 2;
            *(float2*)(C + r0 * 512 + cc)       = make_float2(acc[mt][nt][0], acc[mt][nt][1]);
            *(float2*)(C + (r0 + 8) * 512 + cc) = make_float2(acc[mt][nt][2], acc[mt][nt][3]);
        }
    }
}

// ---------------------------------------------------------------------------
// Row softmax: reads fp32 logits, writes fp16 attn with 64-group permutation.
// ---------------------------------------------------------------------------
__global__ void softmax_kernel()
{
    const int row = blockIdx.x;
    const int tid = threadIdx.x;
    const float* rp = g_attn + (size_t)row * 512;
    __half* op = g_at16 + (size_t)row * 512;

    float4 v = *(const float4*)(rp + tid * 4);
    float m = fmaxf(fmaxf(v.x, v.y), fmaxf(v.z, v.w));
#pragma unroll
    for (int o = 16; o > 0; o >>= 1) m = fmaxf(m, __shfl_xor_sync(0xFFFFFFFFu, m, o));

    __shared__ float sred[4];
    const int wid = tid >> 5, lane = tid & 31;
    if (lane == 0) sred[wid] = m;
    __syncthreads();
    m = fmaxf(fmaxf(sred[0], sred[1]), fmaxf(sred[2], sred[3]));
    __syncthreads();

    v.x = __expf(v.x - m); v.y = __expf(v.y - m);
    v.z = __expf(v.z - m); v.w = __expf(v.w - m);
    float s = v.x + v.y + v.z + v.w;
#pragma unroll
    for (int o = 16; o > 0; o >>= 1) s += __shfl_xor_sync(0xFFFFFFFFu, s, o);
    if (lane == 0) sred[wid] = s;
    __syncthreads();
    s = sred[0] + sred[1] + sred[2] + sred[3];

    const float inv = 1.0f / s;
    const int c0 = tid * 4;
    const float r4[4] = { v.x * inv, v.y * inv, v.z * inv, v.w * inv };
#pragma unroll
    for (int i = 0; i < 4; i++) {
        const int k = c0 + i;
        op[(k & ~63) + pos64(k & 63)] = __float2half_rn(r4[i]);
    }
}

// ---------------------------------------------------------------------------
extern "C" void kernel_launch(void* const* d_in, const int* in_sizes, int n_in,
                              void* d_out, int out_size)
{
    const float* x  = (const float*)d_in[0];
    const float* Wq = (const float*)d_in[1];
    const float* bq = (const float*)d_in[2];
    const float* Wk = (const float*)d_in[3];
    const float* bk = (const float*)d_in[4];
    const float* Wv = (const float*)d_in[5];
    const float* bv = (const float*)d_in[6];
    float* out = (float*)d_out;

    __half *pqp, *pkp, *pvT, *pat16;
    float* pattn;
    cudaGetSymbolAddress((void**)&pqp,   g_qp);
    cudaGetSymbolAddress((void**)&pkp,   g_kp);
    cudaGetSymbolAddress((void**)&pvT,   g_vT);
    cudaGetSymbolAddress((void**)&pattn, g_attn);
    cudaGetSymbolAddress((void**)&pat16, g_at16);

    const int SMEM_G = 2 * 16384;   // 32 KB (B-only double buffer)
    cudaFuncSetAttribute(gemm_logits, cudaFuncAttributeMaxDynamicSharedMemorySize, SMEM_G);
    cudaFuncSetAttribute(gemm_out,    cudaFuncAttributeMaxDynamicSharedMemorySize, SMEM_G);

    // 1) q,k packed fp16 hi/lo (permuted), vT fp16 (permuted)
    qkv_kernel<<<dim3(16, 16, BATCH), 256>>>(x, Wq, bq, Wk, bk, Wv, bv);

    // 2) logits = q k^T per batch (fp16 3-pass hi/lo, A via LDG)
    gemm_logits<<<dim3(4, 4, BATCH), 256, SMEM_G>>>(pqp, pkp, pattn);

    // 3) softmax rows -> fp16 permuted attn
    softmax_kernel<<<BATCH * 512, 128>>>();

    // 4) out = attn @ vT per (b,c), fp16, A via LDG
    gemm_out<<<dim3(4, 4, BATCH * 8), 256, SMEM_G>>>(pat16, pvT, out);
}

// round 15
// speedup vs baseline: 1.2857x; 1.2857x over previous
#include <cuda_runtime.h>
#include <cuda_fp16.h>
#include <cstdint>

#define BATCH 16
#define HW    262144

// ---------------- scratch (device globals; no runtime allocation) ----------
// q,k packed rows: per (b,h), 1024 fp16 = 16 groups x (32 hi | 32 lo), k-permuted
__device__ __half g_qp[(size_t)BATCH * 512 * 1024];
__device__ __half g_kp[(size_t)BATCH * 512 * 1024];
__device__ __half g_vT[(size_t)BATCH * 8 * HW];     // [B,C,W,H] h 64-group-permuted
__device__ float  g_attn[(size_t)BATCH * HW];       // fp32 logits [B,H,H]
__device__ __half g_at16[(size_t)BATCH * HW];       // fp16 attn, j 64-group-permuted

// ---------------- helpers ---------------------------------------------------
__device__ __forceinline__ int fp_t(int kk) { return (kk & 7) >> 1; }
__device__ __forceinline__ int fp_j(int kk) { return ((kk >> 3) << 1) | (kk & 1); }
__device__ __forceinline__ int pos32(int k32) {
    const int s = k32 >> 4, kk = k32 & 15;
    return fp_t(kk) * 8 + s * 4 + fp_j(kk);
}
__device__ __forceinline__ int pos64(int k64) {
    const int s = k64 >> 4, kk = k64 & 15;
    return ((s & 2) << 4) + fp_t(kk) * 8 + ((s & 1) << 2) + fp_j(kk);
}
template <int SO, int GO>
__device__ __forceinline__ void cpa(uint32_t s, const __half* g) {
    asm volatile("cp.async.cg.shared.global [%0+%1], [%2+%3], 16;"
                 :: "r"(s), "n"(SO), "l"(g), "n"(GO) : "memory");
}
#define CPA_COMMIT()  asm volatile("cp.async.commit_group;" ::: "memory")
#define CPA_WAIT0()   asm volatile("cp.async.wait_group 0;" ::: "memory")

__device__ __forceinline__ uint32_t smem_u32(const void* p) {
    uint32_t a;
    asm("{ .reg .u64 t; cvta.to.shared.u64 t, %1; cvt.u32.u64 %0, t; }" : "=r"(a) : "l"(p));
    return a;
}
__device__ __forceinline__ uint32_t swz128(int r, int ch) {
    const int f = ((r & 1) << 2) | ((r >> 1) & 3);
    return (uint32_t)(r * 128 + ((ch ^ f) << 4));
}
__device__ __forceinline__ uint4 lds128(uint32_t a) {
    uint4 v;
    asm volatile("ld.shared.v4.b32 {%0,%1,%2,%3}, [%4];"
                 : "=r"(v.x), "=r"(v.y), "=r"(v.z), "=r"(v.w) : "r"(a));
    return v;
}
#define MMAH(c, a0, a1, a2, a3, b0, b1) \
    asm volatile("mma.sync.aligned.m16n8k16.row.col.f32.f16.f16.f32 " \
                 "{%0,%1,%2,%3},{%4,%5,%6,%7},{%8,%9},{%0,%1,%2,%3};" \
                 : "+f"((c)[0]), "+f"((c)[1]), "+f"((c)[2]), "+f"((c)[3]) \
                 : "r"(a0), "r"(a1), "r"(a2), "r"(a3), "r"(b0), "r"(b1))

// ---------------------------------------------------------------------------
// Fused q/k/v 1x1 convs -> fp16 operands in GEMM-ready permuted layouts.
// Each thread handles a w-pair (float2 x loads, half2 stores).  v staged in
// smem and written as half2 h-pairs (pos64(h+1)=pos64(h)+1 for even h).
// ---------------------------------------------------------------------------
__global__ void __launch_bounds__(256)
qkv_kernel(const float* __restrict__ x,
           const float* __restrict__ Wq, const float* __restrict__ bq,
           const float* __restrict__ Wk, const float* __restrict__ bk,
           const float* __restrict__ Wv, const float* __restrict__ bv)
{
    __shared__ float sWq[8], sWk[8], sWv[64], sBv[8], sB2[2];
    __shared__ __half sv[8][32][34];     // [c][hl][wl], padded
    const int tid = threadIdx.x;
    if (tid < 8) { sWq[tid] = Wq[tid]; sWk[tid] = Wk[tid]; sBv[tid] = bv[tid]; }
    if (tid >= 8 && tid < 72) sWv[tid - 8] = Wv[tid - 8];
    if (tid == 72) sB2[0] = bq[0];
    if (tid == 73) sB2[1] = bk[0];
    __syncthreads();

    const int b = blockIdx.z, h0 = blockIdx.y * 32, w0 = blockIdx.x * 32;
    const int jp = tid & 15;            // w-pair index
    const int i0 = tid >> 4;            // 16 rows

    const int g   = w0 >> 5;            // q/k group (whole CTA = one group)
    const int lpq = pos32(2 * jp);      // even -> pair-adjacent

#pragma unroll
    for (int ii = 0; ii < 2; ii++) {
        const int i = i0 + ii * 16;     // hl
        const int h = h0 + i;
        const int w = w0 + jp * 2;
        const float2* xp = (const float2*)(x + ((size_t)b * 8) * HW + (size_t)h * 512 + w);
        float2 xv[8];
#pragma unroll
        for (int c = 0; c < 8; c++) xv[c] = xp[(size_t)c * (HW / 2)];

        float q0 = sB2[0], q1 = sB2[0], k0 = sB2[1], k1 = sB2[1];
#pragma unroll
        for (int c = 0; c < 8; c++) {
            q0 += xv[c].x * sWq[c]; q1 += xv[c].y * sWq[c];
            k0 += xv[c].x * sWk[c]; k1 += xv[c].y * sWk[c];
        }
        const size_t rb = ((size_t)b * 512 + h) * 1024 + g * 64 + lpq;
        const __half2 qh = __floats2half2_rn(q0, q1);
        const __half2 kh = __floats2half2_rn(k0, k1);
        *(__half2*)(g_qp + rb)      = qh;
        *(__half2*)(g_qp + rb + 32) = __floats2half2_rn(q0 - __half2float(__low2half(qh)),
                                                        q1 - __half2float(__high2half(qh)));
        *(__half2*)(g_kp + rb)      = kh;
        *(__half2*)(g_kp + rb + 32) = __floats2half2_rn(k0 - __half2float(__low2half(kh)),
                                                        k1 - __half2float(__high2half(kh)));

#pragma unroll
        for (int o = 0; o < 8; o++) {
            float v0 = sBv[o], v1 = sBv[o];
#pragma unroll
            for (int c = 0; c < 8; c++) { v0 += xv[c].x * sWv[o * 8 + c]; v1 += xv[c].y * sWv[o * 8 + c]; }
            *(__half2*)(&sv[o][i][jp * 2]) = __floats2half2_rn(v0, v1);
        }
    }
    __syncthreads();

    // write vT[b,c,w, h0 + pos64local(h)]: half2 h-pairs, 64B dense per (c,w)
    const int c     = tid >> 5;
    const int lane  = tid & 31;
    const int pid   = lane & 15;        // h-pair: hl = 2*pid
    const int whalf = lane >> 4;
    const int lpv   = pos64(2 * pid);
#pragma unroll
    for (int r = 0; r < 16; r++) {
        const int wl = whalf * 16 + r;
        const __half2 val = __halves2half2(sv[c][2 * pid][wl], sv[c][2 * pid + 1][wl]);
        *(__half2*)(g_vT + (((size_t)b * 8 + c) * 512 + (w0 + wl)) * 512 + h0 + lpv) = val;
    }
}

// ---------------------------------------------------------------------------
// GEMM1 (logits, fp16 hi/lo 3-pass).  256 thr, 8 warps 4(m)x2(n), tile 32x64.
// MMA phases swept with nt pairs innermost -> same-acc separation = 4 MMAs.
// ---------------------------------------------------------------------------
__global__ void __launch_bounds__(256, 2)
gemm_logits(const __half* __restrict__ Ab, const __half* __restrict__ Bb,
            float* __restrict__ Cb)
{
    constexpr uint32_t TA = 16384, SB = 32768;

    extern __shared__ char smem[];
    const uint32_t s0 = smem_u32(smem);

    const int tid  = threadIdx.x;
    const int lane = tid & 31;
    const int wid  = tid >> 5;
    const int wm   = (wid & 3) * 32;
    const int wn   = (wid >> 2) * 64;
    const int gid  = lane >> 2;
    const int tig  = lane & 3;

    const int z = blockIdx.z;
    const size_t m0 = (size_t)blockIdx.y * 128;
    const size_t n0 = (size_t)blockIdx.x * 128;
    const __half* A = Ab + (size_t)z * 512 * 1024;
    const __half* B = Bb + (size_t)z * 512 * 1024;
    float* C = Cb + (size_t)z * HW;

    const uint32_t Ah = s0 + swz128(wm + gid, tig);
    const uint32_t Al = s0 + swz128(wm + gid, 4 + tig);
    const uint32_t Bh = s0 + TA + swz128(wn + gid, tig);
    const uint32_t Bl = s0 + TA + swz128(wn + gid, 4 + tig);

    const int seg  = tid & 7;
    const int row0 = tid >> 3;
    const uint32_t lw = s0 + swz128(row0, seg);
    const __half* Ap = A + (m0 + row0) * 1024 + seg * 8;
    const __half* Bp = B + (n0 + row0) * 1024 + seg * 8;

#define GLOADL(SOFF) do { \
    cpa<(SOFF)+0,          0>(lw, Ap); cpa<(SOFF)+4096,   65536>(lw, Ap); \
    cpa<(SOFF)+8192,  131072>(lw, Ap); cpa<(SOFF)+12288, 196608>(lw, Ap); \
    cpa<(SOFF)+16384,      0>(lw, Bp); cpa<(SOFF)+20480,  65536>(lw, Bp); \
    cpa<(SOFF)+24576, 131072>(lw, Bp); cpa<(SOFF)+28672, 196608>(lw, Bp); \
    Ap += 64; Bp += 64; } while (0)

    float acc[2][8][4] = {};

    auto compute = [&](const uint32_t SC) {
        const uint4 h0 = lds128(Ah + SC),        h1 = lds128(Ah + SC + 1024);
        const uint4 h2 = lds128(Ah + SC + 2048), h3 = lds128(Ah + SC + 3072);
        const uint4 l0 = lds128(Al + SC),        l1 = lds128(Al + SC + 1024);
        const uint4 l2 = lds128(Al + SC + 2048), l3 = lds128(Al + SC + 3072);
#pragma unroll
        for (int q = 0; q < 4; q++) {
            uint4 bh[2], bl[2];
#pragma unroll
            for (int i = 0; i < 2; i++) {
                bh[i] = lds128(Bh + SC + (q * 2 + i) * 1024);
                bl[i] = lds128(Bl + SC + (q * 2 + i) * 1024);
            }
#pragma unroll
            for (int i = 0; i < 2; i++) MMAH(acc[0][q*2+i], h0.x, h1.x, h0.y, h1.y, bh[i].x, bh[i].y);
#pragma unroll
            for (int i = 0; i < 2; i++) MMAH(acc[1][q*2+i], h2.x, h3.x, h2.y, h3.y, bh[i].x, bh[i].y);
#pragma unroll
            for (int i = 0; i < 2; i++) MMAH(acc[0][q*2+i], l0.x, l1.x, l0.y, l1.y, bh[i].x, bh[i].y);
#pragma unroll
            for (int i = 0; i < 2; i++) MMAH(acc[1][q*2+i], l2.x, l3.x, l2.y, l3.y, bh[i].x, bh[i].y);
#pragma unroll
            for (int i = 0; i < 2; i++) MMAH(acc[0][q*2+i], h0.x, h1.x, h0.y, h1.y, bl[i].x, bl[i].y);
#pragma unroll
            for (int i = 0; i < 2; i++) MMAH(acc[1][q*2+i], h2.x, h3.x, h2.y, h3.y, bl[i].x, bl[i].y);
#pragma unroll
            for (int i = 0; i < 2; i++) MMAH(acc[0][q*2+i], h0.z, h1.z, h0.w, h1.w, bh[i].z, bh[i].w);
#pragma unroll
            for (int i = 0; i < 2; i++) MMAH(acc[1][q*2+i], h2.z, h3.z, h2.w, h3.w, bh[i].z, bh[i].w);
#pragma unroll
            for (int i = 0; i < 2; i++) MMAH(acc[0][q*2+i], l0.z, l1.z, l0.w, l1.w, bh[i].z, bh[i].w);
#pragma unroll
            for (int i = 0; i < 2; i++) MMAH(acc[1][q*2+i], l2.z, l3.z, l2.w, l3.w, bh[i].z, bh[i].w);
#pragma unroll
            for (int i = 0; i < 2; i++) MMAH(acc[0][q*2+i], h0.z, h1.z, h0.w, h1.w, bl[i].z, bl[i].w);
#pragma unroll
            for (int i = 0; i < 2; i++) MMAH(acc[1][q*2+i], h2.z, h3.z, h2.w, h3.w, bl[i].z, bl[i].w);
        }
    };

    GLOADL(0); CPA_COMMIT();
    for (int c = 0; c < 16; c += 2) {
        CPA_WAIT0(); __syncthreads();
        if (c + 1 < 16) GLOADL(SB);
        CPA_COMMIT();
        compute(0);
        CPA_WAIT0(); __syncthreads();
        if (c + 2 < 16) GLOADL(0);
        CPA_COMMIT();
        compute(SB);
    }
#undef GLOADL

#pragma unroll
    for (int mt = 0; mt < 2; mt++) {
        const size_t r0 = m0 + wm + mt * 16 + gid;
#pragma unroll
        for (int nt = 0; nt < 8; nt++) {
            const size_t cc = n0 + wn + nt * 8 + tig * 2;
            *(float2*)(C + r0 * 512 + cc)       = make_float2(acc[mt][nt][0], acc[mt][nt][1]);
            *(float2*)(C + (r0 + 8) * 512 + cc) = make_float2(acc[mt][nt][2], acc[mt][nt][3]);
        }
    }
}

// ---------------------------------------------------------------------------
// GEMM2 (out = attn @ vT), fp16 single pass.  Phases swept with nt halves
// innermost -> same-acc separation = 8 MMAs.
// ---------------------------------------------------------------------------
__global__ void __launch_bounds__(256, 2)
gemm_out(const __half* __restrict__ Ab, const __half* __restrict__ Bb,
         float* __restrict__ Cb)
{
    constexpr uint32_t TA = 16384, SB = 32768;

    extern __shared__ char smem[];
    const uint32_t s0 = smem_u32(smem);

    const int tid  = threadIdx.x;
    const int lane = tid & 31;
    const int wid  = tid >> 5;
    const int wm   = (wid & 3) * 32;
    const int wn   = (wid >> 2) * 64;
    const int gid  = lane >> 2;
    const int tig  = lane & 3;

    const int z = blockIdx.z;
    const size_t m0 = (size_t)blockIdx.y * 128;
    const size_t n0 = (size_t)blockIdx.x * 128;
    const __half* A = Ab + (size_t)(z >> 3) * HW;
    const __half* B = Bb + (size_t)z * HW;
    float* C = Cb + (size_t)z * HW;

    const uint32_t A0 = s0 + swz128(wm + gid, tig);
    const uint32_t A1 = s0 + swz128(wm + gid, 4 + tig);
    const uint32_t B0 = s0 + TA + swz128(wn + gid, tig);
    const uint32_t B1 = s0 + TA + swz128(wn + gid, 4 + tig);

    const int seg  = tid & 7;
    const int row0 = tid >> 3;
    const uint32_t lw = s0 + swz128(row0, seg);
    const __half* Ap = A + (m0 + row0) * 512 + seg * 8;
    const __half* Bp = B + (n0 + row0) * 512 + seg * 8;

#define GLOAD(SOFF) do { \
    cpa<(SOFF)+0,          0>(lw, Ap); cpa<(SOFF)+4096,   32768>(lw, Ap); \
    cpa<(SOFF)+8192,   65536>(lw, Ap); cpa<(SOFF)+12288,  98304>(lw, Ap); \
    cpa<(SOFF)+16384,      0>(lw, Bp); cpa<(SOFF)+20480,  32768>(lw, Bp); \
    cpa<(SOFF)+24576,  65536>(lw, Bp); cpa<(SOFF)+28672,  98304>(lw, Bp); \
    Ap += 64; Bp += 64; } while (0)

    float acc[2][8][4] = {};

    auto compute = [&](const uint32_t SC) {
#pragma unroll
        for (int g = 0; g < 2; g++) {
            const uint32_t aB = (g ? A1 : A0) + SC;
            const uint32_t bB = (g ? B1 : B0) + SC;
            const uint4 a0 = lds128(aB),        a1 = lds128(aB + 1024);
            const uint4 a2 = lds128(aB + 2048), a3 = lds128(aB + 3072);
#pragma unroll
            for (int h = 0; h < 2; h++) {
                uint4 bv[4];
#pragma unroll
                for (int i = 0; i < 4; i++) bv[i] = lds128(bB + (h * 4 + i) * 1024);
#pragma unroll
                for (int i = 0; i < 4; i++)
                    MMAH(acc[0][h*4+i], a0.x, a1.x, a0.y, a1.y, bv[i].x, bv[i].y);
#pragma unroll
                for (int i = 0; i < 4; i++)
                    MMAH(acc[1][h*4+i], a2.x, a3.x, a2.y, a3.y, bv[i].x, bv[i].y);
#pragma unroll
                for (int i = 0; i < 4; i++)
                    MMAH(acc[0][h*4+i], a0.z, a1.z, a0.w, a1.w, bv[i].z, bv[i].w);
#pragma unroll
                for (int i = 0; i < 4; i++)
                    MMAH(acc[1][h*4+i], a2.z, a3.z, a2.w, a3.w, bv[i].z, bv[i].w);
            }
        }
    };

    GLOAD(0); CPA_COMMIT();
    for (int c = 0; c < 8; c += 2) {
        CPA_WAIT0(); __syncthreads();
        if (c + 1 < 8) GLOAD(SB);
        CPA_COMMIT();
        compute(0);
        CPA_WAIT0(); __syncthreads();
        if (c + 2 < 8) GLOAD(0);
        CPA_COMMIT();
        compute(SB);
    }
#undef GLOAD

#pragma unroll
    for (int mt = 0; mt < 2; mt++) {
        const size_t r0 = m0 + wm + mt * 16 + gid;
#pragma unroll
        for (int nt = 0; nt < 8; nt++) {
            const size_t cc = n0 + wn + nt * 8 + tig * 2;
            *(float2*)(C + r0 * 512 + cc)       = make_float2(acc[mt][nt][0], acc[mt][nt][1]);
            *(float2*)(C + (r0 + 8) * 512 + cc) = make_float2(acc[mt][nt][2], acc[mt][nt][3]);
        }
    }
}

// ---------------------------------------------------------------------------
// Row softmax: reads fp32 logits, writes fp16 attn (64-group permuted) as
// aligned half2 pairs.
// ---------------------------------------------------------------------------
__global__ void softmax_kernel()
{
    const int row = blockIdx.x;
    const int tid = threadIdx.x;
    const float* rp = g_attn + (size_t)row * 512;
    __half* op = g_at16 + (size_t)row * 512;

    float4 v = *(const float4*)(rp + tid * 4);
    float m = fmaxf(fmaxf(v.x, v.y), fmaxf(v.z, v.w));
#pragma unroll
    for (int o = 16; o > 0; o >>= 1) m = fmaxf(m, __shfl_xor_sync(0xFFFFFFFFu, m, o));

    __shared__ float sred[4];
    const int wid = tid >> 5, lane = tid & 31;
    if (lane == 0) sred[wid] = m;
    __syncthreads();
    m = fmaxf(fmaxf(sred[0], sred[1]), fmaxf(sred[2], sred[3]));
    __syncthreads();

    v.x = __expf(v.x - m); v.y = __expf(v.y - m);
    v.z = __expf(v.z - m); v.w = __expf(v.w - m);
    float s = v.x + v.y + v.z + v.w;
#pragma unroll
    for (int o = 16; o > 0; o >>= 1) s += __shfl_xor_sync(0xFFFFFFFFu, s, o);
    if (lane == 0) sred[wid] = s;
    __syncthreads();
    s = sred[0] + sred[1] + sred[2] + sred[3];

    const float inv = 1.0f / s;
    const int c0 = tid * 4;
    int k = c0;
    *(__half2*)(op + (k & ~63) + pos64(k & 63)) = __floats2half2_rn(v.x * inv, v.y * inv);
    k = c0 + 2;
    *(__half2*)(op + (k & ~63) + pos64(k & 63)) = __floats2half2_rn(v.z * inv, v.w * inv);
}

// ---------------------------------------------------------------------------
extern "C" void kernel_launch(void* const* d_in, const int* in_sizes, int n_in,
                              void* d_out, int out_size)
{
    const float* x  = (const float*)d_in[0];
    const float* Wq = (const float*)d_in[1];
    const float* bq = (const float*)d_in[2];
    const float* Wk = (const float*)d_in[3];
    const float* bk = (const float*)d_in[4];
    const float* Wv = (const float*)d_in[5];
    const float* bv = (const float*)d_in[6];
    float* out = (float*)d_out;

    __half *pqp, *pkp, *pvT, *pat16;
    float* pattn;
    cudaGetSymbolAddress((void**)&pqp,   g_qp);
    cudaGetSymbolAddress((void**)&pkp,   g_kp);
    cudaGetSymbolAddress((void**)&pvT,   g_vT);
    cudaGetSymbolAddress((void**)&pattn, g_attn);
    cudaGetSymbolAddress((void**)&pat16, g_at16);

    const int SMEM_G = 2 * 32768;   // 64 KB double buffer
    cudaFuncSetAttribute(gemm_logits, cudaFuncAttributeMaxDynamicSharedMemorySize, SMEM_G);
    cudaFuncSetAttribute(gemm_out,    cudaFuncAttributeMaxDynamicSharedMemorySize, SMEM_G);

    // 1) q,k packed fp16 hi/lo (permuted), vT fp16 (permuted)
    qkv_kernel<<<dim3(16, 16, BATCH), 256>>>(x, Wq, bq, Wk, bk, Wv, bv);

    // 2) logits = q k^T per batch (fp16 3-pass hi/lo)
    gemm_logits<<<dim3(4, 4, BATCH), 256, SMEM_G>>>(pqp, pkp, pattn);

    // 3) softmax rows -> fp16 permuted attn
    softmax_kernel<<<BATCH * 512, 128>>>();

    // 4) out = attn @ vT per (b,c), fp16 single pass
    gemm_out<<<dim3(4, 4, BATCH * 8), 256, SMEM_G>>>(pat16, pvT, out);
}